// round 8
// baseline (speedup 1.0000x reference)
#include <cuda_runtime.h>
#include <cstdint>

#define BSZ  256
#define TSEQ 512
#define HIDN 256

typedef unsigned long long ull;

// ---- static scratch ----
// xg layout: [t][b][n][4] (gate quads)
__device__ float g_xg[(size_t)TSEQ * BSZ * 1024];
__device__ float g_hist0[(size_t)TSEQ * BSZ * HIDN];
__device__ float g_hist1[(size_t)TSEQ * BSZ * HIDN];

__device__ __forceinline__ float sigm(float x) { return 1.f / (1.f + __expf(-x)); }
__device__ __forceinline__ float ftanh(float x) {
    float e = __expf(-2.f * fabsf(x));
    return copysignf((1.f - e) / (1.f + e), x);
}

// ---- packed fp32x2 (Blackwell) ----
__device__ __forceinline__ ull ffma2(ull a, ull b, ull c) {
    ull d; asm("fma.rn.f32x2 %0, %1, %2, %3;" : "=l"(d) : "l"(a), "l"(b), "l"(c)); return d;
}
__device__ __forceinline__ ull add2(ull a, ull b) {
    ull d; asm("add.rn.f32x2 %0, %1, %2;" : "=l"(d) : "l"(a), "l"(b)); return d;
}
__device__ __forceinline__ ull dup2(float x) {
    ull r; asm("mov.b64 %0, {%1, %1};" : "=l"(r) : "f"(x)); return r;
}
__device__ __forceinline__ float2 unpk(ull v) {
    float2 f; asm("mov.b64 {%0, %1}, %2;" : "=f"(f.x), "=f"(f.y) : "l"(v)); return f;
}

// ---- cluster mbarrier primitives ----
__device__ __forceinline__ uint32_t smem_u32(const void* p) {
    uint32_t a;
    asm("{ .reg .u64 t; cvta.to.shared.u64 t, %1; cvt.u32.u64 %0, t; }" : "=r"(a) : "l"(p));
    return a;
}
__device__ __forceinline__ void mbar_init(uint32_t addr, uint32_t cnt) {
    asm volatile("mbarrier.init.shared.b64 [%0], %1;" :: "r"(addr), "r"(cnt) : "memory");
}
// remote arrive with cluster-scope release (cumulative: publishes CTA's prior global stores
// made visible to this thread via the preceding __syncthreads)
__device__ __forceinline__ void mbar_arrive_peer(uint32_t local_addr, uint32_t rank) {
    asm volatile(
        "{\n\t.reg .b32 r;\n\t"
        "mapa.shared::cluster.u32 r, %0, %1;\n\t"
        "mbarrier.arrive.release.cluster.shared::cluster.b64 _, [r];\n\t"
        "}" :: "r"(local_addr), "r"(rank) : "memory");
}
// parity wait with cluster-scope acquire (orders subsequent global h loads)
__device__ __forceinline__ void mbar_wait_parity(uint32_t addr, uint32_t parity) {
    asm volatile(
        "{\n\t"
        ".reg .pred P;\n"
        "WAIT_%=:\n\t"
        "mbarrier.try_wait.parity.acquire.cluster.shared::cta.b64 P, [%0], %1, 0x989680;\n\t"
        "@P bra.uni DONE_%=;\n\t"
        "bra.uni WAIT_%=;\n"
        "DONE_%=:\n\t"
        "}" :: "r"(addr), "r"(parity) : "memory");
}

// ---- GEMM: xg[m*256 + n] (float4 gate quad) = A_row(m).W[g*256+n] + biases ----
template<int K, bool XMODE>
__global__ void __launch_bounds__(256, 2) gemm_xg(
    const float* __restrict__ A, const float* __restrict__ W,
    const float* __restrict__ b1, const float* __restrict__ b2,
    float* __restrict__ out)
{
    __shared__ float As[16][132];
    __shared__ float Ws[16][132];   // c = g*32 + (n-n0)
    const int m0 = blockIdx.x * 128, n0 = blockIdx.y * 32;
    const int tid = threadIdx.x;
    const int tm = tid >> 4, tn = tid & 15;

    int rrv[2], kqv[2];
#pragma unroll
    for (int i = 0; i < 2; i++) { int idx = tid + (i << 8); rrv[i] = idx >> 2; kqv[i] = (idx & 3) << 2; }
    size_t aoffv[2], woffv[2];
#pragma unroll
    for (int i = 0; i < 2; i++) {
        int row = m0 + rrv[i];
        if (XMODE) aoffv[i] = ((size_t)(row & 255) * TSEQ + (row >> 8)) * K;
        else       aoffv[i] = (size_t)row * K;
        int wrow = ((rrv[i] >> 5) << 8) + n0 + (rrv[i] & 31);
        woffv[i] = (size_t)wrow * K;
    }

    ull acc[8][4];
#pragma unroll
    for (int i = 0; i < 8; i++)
#pragma unroll
        for (int j = 0; j < 4; j++) acc[i][j] = 0ull;

    float4 pa[2], pw[2];
#pragma unroll
    for (int i = 0; i < 2; i++) {
        pa[i] = *reinterpret_cast<const float4*>(A + aoffv[i] + kqv[i]);
        pw[i] = *reinterpret_cast<const float4*>(W + woffv[i] + kqv[i]);
    }

    for (int kt = 0; kt < K; kt += 16) {
#pragma unroll
        for (int i = 0; i < 2; i++) {
            int k = kqv[i], rr = rrv[i];
            As[k+0][rr]=pa[i].x; As[k+1][rr]=pa[i].y; As[k+2][rr]=pa[i].z; As[k+3][rr]=pa[i].w;
            Ws[k+0][rr]=pw[i].x; Ws[k+1][rr]=pw[i].y; Ws[k+2][rr]=pw[i].z; Ws[k+3][rr]=pw[i].w;
        }
        __syncthreads();
        if (kt + 16 < K) {
#pragma unroll
            for (int i = 0; i < 2; i++) {
                pa[i] = *reinterpret_cast<const float4*>(A + aoffv[i] + kt + 16 + kqv[i]);
                pw[i] = *reinterpret_cast<const float4*>(W + woffv[i] + kt + 16 + kqv[i]);
            }
        }
#pragma unroll
        for (int k = 0; k < 16; k++) {
            float a[8];
            *reinterpret_cast<float4*>(&a[0]) = *reinterpret_cast<const float4*>(&As[k][tm << 3]);
            *reinterpret_cast<float4*>(&a[4]) = *reinterpret_cast<const float4*>(&As[k][(tm << 3) + 4]);
            ull w2[4];
#pragma unroll
            for (int g = 0; g < 4; g++)
                w2[g] = *reinterpret_cast<const ull*>(&Ws[k][(g << 5) + (tn << 1)]);
#pragma unroll
            for (int i = 0; i < 8; i++) {
                ull ad = dup2(a[i]);
#pragma unroll
                for (int g = 0; g < 4; g++) acc[i][g] = ffma2(ad, w2[g], acc[i][g]);
            }
        }
        __syncthreads();
    }

    const int n = n0 + (tn << 1);
    float bv0[4], bv1[4];
#pragma unroll
    for (int g = 0; g < 4; g++) {
        bv0[g] = b1[(g << 8) + n]     + b2[(g << 8) + n];
        bv1[g] = b1[(g << 8) + n + 1] + b2[(g << 8) + n + 1];
    }
    float4* out4 = reinterpret_cast<float4*>(out);
#pragma unroll
    for (int i = 0; i < 8; i++) {
        int m = m0 + (tm << 3) + i;
        float2 q0 = unpk(acc[i][0]), q1 = unpk(acc[i][1]);
        float2 q2 = unpk(acc[i][2]), q3 = unpk(acc[i][3]);
        out4[(size_t)m * 256 + n]     = make_float4(q0.x+bv0[0], q1.x+bv0[1], q2.x+bv0[2], q3.x+bv0[3]);
        out4[(size_t)m * 256 + n + 1] = make_float4(q0.y+bv1[0], q1.y+bv1[1], q2.y+bv1[2], q3.y+bv1[3]);
    }
}

// ---- persistent LSTM recurrence ----
// 128 CTAs = 16 clusters of 8 (one batch group per cluster). Handoff = cluster mbarrier
// (count 8, one arrive per producer CTA per step). h data flows via L2 as before.
__global__ void __launch_bounds__(256, 1) __cluster_dims__(8, 1, 1) rec_kernel(
    const float* __restrict__ xg, const float* __restrict__ Whh,
    float* __restrict__ hist)
{
    extern __shared__ float sm[];
    float* Wsh = sm + 4;        // [k][nn*4+g]  32768 floats (16B-aligned)
    float* hsh = Wsh + 32768;   // 8 warps x [16][36] = 4608
    float* red = hsh + 4608;    // [kg][cell][4] = 16384
    const uint32_t mbar = smem_u32(sm);   // 8B mbarrier in first slot

    const int bi = blockIdx.x >> 3, ni = blockIdx.x & 7;  // ni == cluster rank
    const int b0 = bi << 4, n0 = ni << 5;
    const int tid = threadIdx.x;
    const int kg  = tid >> 5;
    const int cid = tid & 31;
    const int bb  = (cid >> 4) << 3;
    const int pn  = cid & 15;

    if (tid == 0) mbar_init(mbar, 8);

    // Wsh[k][nn*4+g] = Whh[g*256 + n0 + nn][k]
    for (int idx = tid; idx < 8192; idx += 256) {
        int kq = idx & 63, c = idx >> 6;
        int nn = c >> 2, g = c & 3;
        float4 v = *reinterpret_cast<const float4*>(
            Whh + (size_t)((g << 8) + n0 + nn) * HIDN + (kq << 2));
        int k = kq << 2;
        Wsh[(k+0)*128+c]=v.x; Wsh[(k+1)*128+c]=v.y; Wsh[(k+2)*128+c]=v.z; Wsh[(k+3)*128+c]=v.w;
    }
    __syncthreads();
    // all 8 CTAs' mbarriers initialized before any arrive
    asm volatile("barrier.cluster.arrive.aligned;" ::: "memory");
    asm volatile("barrier.cluster.wait.aligned;"   ::: "memory");

    const int p0i = tid << 1;
    const int eb  = p0i >> 5, enn = p0i & 31;

    float* hshW = hsh + kg * 576;
    const float4* xg4 = reinterpret_cast<const float4*>(xg);
    float creg[2] = {0.f, 0.f};

    for (int t = 0; t < TSEQ; t++) {
        // prefetch gate quads (independent of h)
        size_t xi = ((size_t)t * BSZ + b0 + eb) * 256 + n0 + enn;
        ulonglong2 xq0 = *reinterpret_cast<const ulonglong2*>(&xg4[xi]);
        ulonglong2 xq1 = *reinterpret_cast<const ulonglong2*>(&xg4[xi + 1]);

        ull acc2[8][4];
#pragma unroll
        for (int i = 0; i < 8; i++)
#pragma unroll
            for (int j = 0; j < 4; j++) acc2[i][j] = 0ull;

        if (t > 0) {
            // wait for all 8 producers of step t-1 (local SMEM mbarrier, acquire.cluster)
            mbar_wait_parity(mbar, (t - 1) & 1);

            // stage own k-slice: 16 batches x 32 k
            const float* hp = hist + ((size_t)(t - 1) * BSZ + b0) * HIDN + (kg << 5);
#pragma unroll
            for (int i = 0; i < 4; i++) {
                int f  = cid + (i << 5);
                int b  = f >> 3, c4 = (f & 7) << 2;
                *reinterpret_cast<float4*>(hshW + b * 36 + c4) =
                    *reinterpret_cast<const float4*>(hp + (b << 8) + c4);
            }
            __syncwarp();

            const float* hpL = hshW + bb * 36;
            const float* wp  = Wsh + ((kg << 5) * 128) + (pn << 3);
#pragma unroll 8
            for (int k = 0; k < 32; k++) {
                ulonglong2 wa = *reinterpret_cast<const ulonglong2*>(wp);
                ulonglong2 wb = *reinterpret_cast<const ulonglong2*>(wp + 4);
                wp += 128;
#pragma unroll
                for (int i = 0; i < 8; i++) {
                    ull hd = dup2(hpL[i * 36 + k]);
                    acc2[i][0] = ffma2(hd, wa.x, acc2[i][0]);
                    acc2[i][1] = ffma2(hd, wa.y, acc2[i][1]);
                    acc2[i][2] = ffma2(hd, wb.x, acc2[i][2]);
                    acc2[i][3] = ffma2(hd, wb.y, acc2[i][3]);
                }
            }
        }

        // gate-quad partials: red[kg][cell][4]
#pragma unroll
        for (int i = 0; i < 8; i++) {
            float* rp = red + (kg << 11) + (((bb + i) << 5) + (pn << 1)) * 4;
            *reinterpret_cast<ulonglong2*>(rp)     = make_ulonglong2(acc2[i][0], acc2[i][1]);
            *reinterpret_cast<ulonglong2*>(rp + 4) = make_ulonglong2(acc2[i][2], acc2[i][3]);
        }
        __syncthreads();

        // epilogue: packed quad reduction + activations, c in registers
        float* ho = hist + ((size_t)t * BSZ + b0 + eb) * HIDN + n0 + enn;
        float hout[2];
#pragma unroll
        for (int pp = 0; pp < 2; pp++) {
            int cell = (eb << 5) + enn + pp;
            ull s01 = pp ? xq1.x : xq0.x;
            ull s23 = pp ? xq1.y : xq0.y;
            const float* rb = red + cell * 4;
#pragma unroll
            for (int s = 0; s < 8; s++) {
                ulonglong2 r = *reinterpret_cast<const ulonglong2*>(rb + (s << 11));
                s01 = add2(s01, r.x);
                s23 = add2(s23, r.y);
            }
            float2 g01 = unpk(s01), g23 = unpk(s23);
            float cn = sigm(g01.y) * creg[pp] + sigm(g01.x) * ftanh(g23.x);
            creg[pp] = cn;
            hout[pp] = sigm(g23.y) * ftanh(cn);
        }
        *reinterpret_cast<float2*>(ho) = make_float2(hout[0], hout[1]);

        __syncthreads();   // all h stores of this CTA are done (cta-scope HB for tid 0..7)
        if (t < TSEQ - 1 && tid < 8)
            mbar_arrive_peer(mbar, (uint32_t)tid);   // release.cluster, cumulative
    }

    // keep SMEM alive until every peer's remote arrives have landed
    asm volatile("barrier.cluster.arrive.aligned;" ::: "memory");
    asm volatile("barrier.cluster.wait.aligned;"   ::: "memory");
}

// ---- head ----
__global__ void head_kernel(const float* __restrict__ Wh, const float* __restrict__ bh,
                            float* __restrict__ out)
{
    __shared__ float rs[8];
    int b = blockIdx.x, tid = threadIdx.x;
    float v = g_hist1[((size_t)(TSEQ - 1) * BSZ + b) * HIDN + tid] * Wh[tid];
#pragma unroll
    for (int o = 16; o > 0; o >>= 1) v += __shfl_down_sync(0xffffffffu, v, o);
    if ((tid & 31) == 0) rs[tid >> 5] = v;
    __syncthreads();
    if (tid < 8) {
        float s = rs[tid];
#pragma unroll
        for (int o = 4; o > 0; o >>= 1) s += __shfl_down_sync(0xffu, s, o);
        if (tid == 0) out[b] = s + bh[0];
    }
}

extern "C" void kernel_launch(void* const* d_in, const int* in_sizes, int n_in,
                              void* d_out, int out_size)
{
    const float* x      = (const float*)d_in[0];
    const float* W_ih0  = (const float*)d_in[1];
    const float* W_hh0  = (const float*)d_in[2];
    const float* b_ih0  = (const float*)d_in[3];
    const float* b_hh0  = (const float*)d_in[4];
    const float* W_ih1  = (const float*)d_in[5];
    const float* W_hh1  = (const float*)d_in[6];
    const float* b_ih1  = (const float*)d_in[7];
    const float* b_hh1  = (const float*)d_in[8];
    const float* W_head = (const float*)d_in[9];
    const float* b_head = (const float*)d_in[10];
    float* out = (float*)d_out;

    void *pxg, *ph0, *ph1;
    cudaGetSymbolAddress(&pxg, g_xg);
    cudaGetSymbolAddress(&ph0, g_hist0);
    cudaGetSymbolAddress(&ph1, g_hist1);
    float* xg = (float*)pxg; float* h0 = (float*)ph0; float* h1 = (float*)ph1;

    const int SMEM = 53764 * 4;   // 215056 B (mbar pad + W + staging + red)
    cudaFuncSetAttribute(rec_kernel, cudaFuncAttributeMaxDynamicSharedMemorySize, SMEM);

    dim3 gg(1024, 8);
    gemm_xg<64,  true ><<<gg, 256>>>(x,  W_ih0, b_ih0, b_hh0, xg);
    rec_kernel<<<128, 256, SMEM>>>(xg, W_hh0, h0);
    gemm_xg<256, false><<<gg, 256>>>(h0, W_ih1, b_ih1, b_hh1, xg);
    rec_kernel<<<128, 256, SMEM>>>(xg, W_hh1, h1);
    head_kernel<<<256, 256>>>(W_head, b_head, out);
}

// round 9
// speedup vs baseline: 1.6598x; 1.6598x over previous
#include <cuda_runtime.h>
#include <cstdint>

#define BSZ  256
#define TSEQ 512
#define HIDN 256

typedef unsigned long long ull;

// ---- static scratch ----
// xg layout: [t][b][n][4] (gate quads)
__device__ float g_xg[(size_t)TSEQ * BSZ * 1024];
__device__ float g_hist0[(size_t)TSEQ * BSZ * HIDN];
__device__ float g_hist1[(size_t)TSEQ * BSZ * HIDN];
__device__ unsigned g_bar[128];   // [batch-group][producer ni]

__global__ void reset_bar() { if (threadIdx.x < 128) g_bar[threadIdx.x] = 0u; }

__device__ __forceinline__ float sigm(float x) { return 1.f / (1.f + __expf(-x)); }
__device__ __forceinline__ float ftanh(float x) {
    float e = __expf(-2.f * fabsf(x));
    return copysignf((1.f - e) / (1.f + e), x);
}

// ---- packed fp32x2 (Blackwell) ----
__device__ __forceinline__ ull ffma2(ull a, ull b, ull c) {
    ull d; asm("fma.rn.f32x2 %0, %1, %2, %3;" : "=l"(d) : "l"(a), "l"(b), "l"(c)); return d;
}
__device__ __forceinline__ ull add2(ull a, ull b) {
    ull d; asm("add.rn.f32x2 %0, %1, %2;" : "=l"(d) : "l"(a), "l"(b)); return d;
}
__device__ __forceinline__ ull dup2(float x) {
    ull r; asm("mov.b64 %0, {%1, %1};" : "=l"(r) : "f"(x)); return r;
}
__device__ __forceinline__ float2 unpk(ull v) {
    float2 f; asm("mov.b64 {%0, %1}, %2;" : "=f"(f.x), "=f"(f.y) : "l"(v)); return f;
}

// ---- scoped sync ----
__device__ __forceinline__ unsigned ld_acq(const unsigned* p) {
    unsigned v; asm volatile("ld.acquire.gpu.global.b32 %0, [%1];" : "=r"(v) : "l"(p)); return v;
}
__device__ __forceinline__ void red_rel_add(unsigned* p, unsigned v) {
    asm volatile("red.release.gpu.global.add.u32 [%0], %1;" :: "l"(p), "r"(v) : "memory");
}

// ---- GEMM: xg[m*256 + n] (float4 gate quad) = A_row(m).W[g*256+n] + biases ----
template<int K, bool XMODE>
__global__ void __launch_bounds__(256, 2) gemm_xg(
    const float* __restrict__ A, const float* __restrict__ W,
    const float* __restrict__ b1, const float* __restrict__ b2,
    float* __restrict__ out)
{
    __shared__ float As[16][132];
    __shared__ float Ws[16][132];   // c = g*32 + (n-n0)
    const int m0 = blockIdx.x * 128, n0 = blockIdx.y * 32;
    const int tid = threadIdx.x;
    const int tm = tid >> 4, tn = tid & 15;

    int rrv[2], kqv[2];
#pragma unroll
    for (int i = 0; i < 2; i++) { int idx = tid + (i << 8); rrv[i] = idx >> 2; kqv[i] = (idx & 3) << 2; }
    size_t aoffv[2], woffv[2];
#pragma unroll
    for (int i = 0; i < 2; i++) {
        int row = m0 + rrv[i];
        if (XMODE) aoffv[i] = ((size_t)(row & 255) * TSEQ + (row >> 8)) * K;
        else       aoffv[i] = (size_t)row * K;
        int wrow = ((rrv[i] >> 5) << 8) + n0 + (rrv[i] & 31);
        woffv[i] = (size_t)wrow * K;
    }

    ull acc[8][4];
#pragma unroll
    for (int i = 0; i < 8; i++)
#pragma unroll
        for (int j = 0; j < 4; j++) acc[i][j] = 0ull;

    float4 pa[2], pw[2];
#pragma unroll
    for (int i = 0; i < 2; i++) {
        pa[i] = *reinterpret_cast<const float4*>(A + aoffv[i] + kqv[i]);
        pw[i] = *reinterpret_cast<const float4*>(W + woffv[i] + kqv[i]);
    }

    for (int kt = 0; kt < K; kt += 16) {
#pragma unroll
        for (int i = 0; i < 2; i++) {
            int k = kqv[i], rr = rrv[i];
            As[k+0][rr]=pa[i].x; As[k+1][rr]=pa[i].y; As[k+2][rr]=pa[i].z; As[k+3][rr]=pa[i].w;
            Ws[k+0][rr]=pw[i].x; Ws[k+1][rr]=pw[i].y; Ws[k+2][rr]=pw[i].z; Ws[k+3][rr]=pw[i].w;
        }
        __syncthreads();
        if (kt + 16 < K) {
#pragma unroll
            for (int i = 0; i < 2; i++) {
                pa[i] = *reinterpret_cast<const float4*>(A + aoffv[i] + kt + 16 + kqv[i]);
                pw[i] = *reinterpret_cast<const float4*>(W + woffv[i] + kt + 16 + kqv[i]);
            }
        }
#pragma unroll
        for (int k = 0; k < 16; k++) {
            float a[8];
            *reinterpret_cast<float4*>(&a[0]) = *reinterpret_cast<const float4*>(&As[k][tm << 3]);
            *reinterpret_cast<float4*>(&a[4]) = *reinterpret_cast<const float4*>(&As[k][(tm << 3) + 4]);
            ull w2[4];
#pragma unroll
            for (int g = 0; g < 4; g++)
                w2[g] = *reinterpret_cast<const ull*>(&Ws[k][(g << 5) + (tn << 1)]);
#pragma unroll
            for (int i = 0; i < 8; i++) {
                ull ad = dup2(a[i]);
#pragma unroll
                for (int g = 0; g < 4; g++) acc[i][g] = ffma2(ad, w2[g], acc[i][g]);
            }
        }
        __syncthreads();
    }

    const int n = n0 + (tn << 1);
    float bv0[4], bv1[4];
#pragma unroll
    for (int g = 0; g < 4; g++) {
        bv0[g] = b1[(g << 8) + n]     + b2[(g << 8) + n];
        bv1[g] = b1[(g << 8) + n + 1] + b2[(g << 8) + n + 1];
    }
    float4* out4 = reinterpret_cast<float4*>(out);
#pragma unroll
    for (int i = 0; i < 8; i++) {
        int m = m0 + (tm << 3) + i;
        float2 q0 = unpk(acc[i][0]), q1 = unpk(acc[i][1]);
        float2 q2 = unpk(acc[i][2]), q3 = unpk(acc[i][3]);
        out4[(size_t)m * 256 + n]     = make_float4(q0.x+bv0[0], q1.x+bv0[1], q2.x+bv0[2], q3.x+bv0[3]);
        out4[(size_t)m * 256 + n + 1] = make_float4(q0.y+bv1[0], q1.y+bv1[1], q2.y+bv1[2], q3.y+bv1[3]);
    }
}

// ---- persistent LSTM recurrence ----
// 128 CTAs = 16 batch-groups x 8 n-groups. Warp kg owns k-slice [32kg,32kg+32),
// produced by exactly CTA ni==kg of the same group -> warp polls ONLY that counter.
__global__ void __launch_bounds__(256, 1) rec_kernel(
    const float* __restrict__ xg, const float* __restrict__ Whh,
    float* __restrict__ hist)
{
    extern __shared__ float sm[];
    float* Wsh = sm;            // [k][nn*4+g]  32768 floats
    float* hsh = Wsh + 32768;   // 8 warps x [16][36] = 4608
    float* red = hsh + 4608;    // [kg][cell][4] = 16384

    const int bi = blockIdx.x >> 3, ni = blockIdx.x & 7;
    const int b0 = bi << 4, n0 = ni << 5;
    const int tid = threadIdx.x;
    const int kg  = tid >> 5;
    const int cid = tid & 31;
    const int bb  = (cid >> 4) << 3;
    const int pn  = cid & 15;

    // Wsh[k][nn*4+g] = Whh[g*256 + n0 + nn][k]
    for (int idx = tid; idx < 8192; idx += 256) {
        int kq = idx & 63, c = idx >> 6;
        int nn = c >> 2, g = c & 3;
        float4 v = *reinterpret_cast<const float4*>(
            Whh + (size_t)((g << 8) + n0 + nn) * HIDN + (kq << 2));
        int k = kq << 2;
        Wsh[(k+0)*128+c]=v.x; Wsh[(k+1)*128+c]=v.y; Wsh[(k+2)*128+c]=v.z; Wsh[(k+3)*128+c]=v.w;
    }
    __syncthreads();

    const int p0i = tid << 1;
    const int eb  = p0i >> 5, enn = p0i & 31;

    const unsigned* prodcnt = g_bar + (bi << 3) + kg;   // this warp's sole producer
    unsigned* mycnt = g_bar + (bi << 3) + ni;

    float* hshW = hsh + kg * 576;
    const float4* xg4 = reinterpret_cast<const float4*>(xg);
    float creg[2] = {0.f, 0.f};

    for (int t = 0; t < TSEQ; t++) {
        // prefetch gate quads (independent of h)
        size_t xi = ((size_t)t * BSZ + b0 + eb) * 256 + n0 + enn;
        ulonglong2 xq0 = *reinterpret_cast<const ulonglong2*>(&xg4[xi]);
        ulonglong2 xq1 = *reinterpret_cast<const ulonglong2*>(&xg4[xi + 1]);

        ull acc2[8][4];
#pragma unroll
        for (int i = 0; i < 8; i++)
#pragma unroll
            for (int j = 0; j < 4; j++) acc2[i][j] = 0ull;

        if (t > 0) {
            // wait only on this warp's producer having finished step t-1
            const unsigned tgt = (unsigned)t;
            while (ld_acq(prodcnt) < tgt) {}

            // stage own k-slice: 16 batches x 32 k (warp-private)
            const float* hp = hist + ((size_t)(t - 1) * BSZ + b0) * HIDN + (kg << 5);
#pragma unroll
            for (int i = 0; i < 4; i++) {
                int f  = cid + (i << 5);
                int b  = f >> 3, c4 = (f & 7) << 2;
                *reinterpret_cast<float4*>(hshW + b * 36 + c4) =
                    *reinterpret_cast<const float4*>(hp + (b << 8) + c4);
            }
            __syncwarp();

            const float* hpL = hshW + bb * 36;
            const float* wp  = Wsh + ((kg << 5) * 128) + (pn << 3);
#pragma unroll 8
            for (int k = 0; k < 32; k++) {
                ulonglong2 wa = *reinterpret_cast<const ulonglong2*>(wp);
                ulonglong2 wb = *reinterpret_cast<const ulonglong2*>(wp + 4);
                wp += 128;
#pragma unroll
                for (int i = 0; i < 8; i++) {
                    ull hd = dup2(hpL[i * 36 + k]);
                    acc2[i][0] = ffma2(hd, wa.x, acc2[i][0]);
                    acc2[i][1] = ffma2(hd, wa.y, acc2[i][1]);
                    acc2[i][2] = ffma2(hd, wb.x, acc2[i][2]);
                    acc2[i][3] = ffma2(hd, wb.y, acc2[i][3]);
                }
            }
        }

        // gate-quad partials: red[kg][cell][4]
#pragma unroll
        for (int i = 0; i < 8; i++) {
            float* rp = red + (kg << 11) + (((bb + i) << 5) + (pn << 1)) * 4;
            *reinterpret_cast<ulonglong2*>(rp)     = make_ulonglong2(acc2[i][0], acc2[i][1]);
            *reinterpret_cast<ulonglong2*>(rp + 4) = make_ulonglong2(acc2[i][2], acc2[i][3]);
        }
        __syncthreads();

        // epilogue: packed quad reduction + activations, c in registers
        float* ho = hist + ((size_t)t * BSZ + b0 + eb) * HIDN + n0 + enn;
        float hout[2];
#pragma unroll
        for (int pp = 0; pp < 2; pp++) {
            int cell = (eb << 5) + enn + pp;
            ull s01 = pp ? xq1.x : xq0.x;
            ull s23 = pp ? xq1.y : xq0.y;
            const float* rb = red + cell * 4;
#pragma unroll
            for (int s = 0; s < 8; s++) {
                ulonglong2 r = *reinterpret_cast<const ulonglong2*>(rb + (s << 11));
                s01 = add2(s01, r.x);
                s23 = add2(s23, r.y);
            }
            float2 g01 = unpk(s01), g23 = unpk(s23);
            float cn = sigm(g01.y) * creg[pp] + sigm(g01.x) * ftanh(g23.x);
            creg[pp] = cn;
            hout[pp] = sigm(g23.y) * ftanh(cn);
        }
        *reinterpret_cast<float2*>(ho) = make_float2(hout[0], hout[1]);

        __syncthreads();                              // all h stores + red reads done
        if (tid == 0) red_rel_add(mycnt, 1u);         // publish step t (own counter)
    }
}

// ---- head ----
__global__ void head_kernel(const float* __restrict__ Wh, const float* __restrict__ bh,
                            float* __restrict__ out)
{
    __shared__ float rs[8];
    int b = blockIdx.x, tid = threadIdx.x;
    float v = g_hist1[((size_t)(TSEQ - 1) * BSZ + b) * HIDN + tid] * Wh[tid];
#pragma unroll
    for (int o = 16; o > 0; o >>= 1) v += __shfl_down_sync(0xffffffffu, v, o);
    if ((tid & 31) == 0) rs[tid >> 5] = v;
    __syncthreads();
    if (tid < 8) {
        float s = rs[tid];
#pragma unroll
        for (int o = 4; o > 0; o >>= 1) s += __shfl_down_sync(0xffu, s, o);
        if (tid == 0) out[b] = s + bh[0];
    }
}

extern "C" void kernel_launch(void* const* d_in, const int* in_sizes, int n_in,
                              void* d_out, int out_size)
{
    const float* x      = (const float*)d_in[0];
    const float* W_ih0  = (const float*)d_in[1];
    const float* W_hh0  = (const float*)d_in[2];
    const float* b_ih0  = (const float*)d_in[3];
    const float* b_hh0  = (const float*)d_in[4];
    const float* W_ih1  = (const float*)d_in[5];
    const float* W_hh1  = (const float*)d_in[6];
    const float* b_ih1  = (const float*)d_in[7];
    const float* b_hh1  = (const float*)d_in[8];
    const float* W_head = (const float*)d_in[9];
    const float* b_head = (const float*)d_in[10];
    float* out = (float*)d_out;

    void *pxg, *ph0, *ph1;
    cudaGetSymbolAddress(&pxg, g_xg);
    cudaGetSymbolAddress(&ph0, g_hist0);
    cudaGetSymbolAddress(&ph1, g_hist1);
    float* xg = (float*)pxg; float* h0 = (float*)ph0; float* h1 = (float*)ph1;

    const int SMEM = 53760 * 4;   // 215040 B
    cudaFuncSetAttribute(rec_kernel, cudaFuncAttributeMaxDynamicSharedMemorySize, SMEM);

    dim3 gg(1024, 8);
    gemm_xg<64,  true ><<<gg, 256>>>(x,  W_ih0, b_ih0, b_hh0, xg);
    reset_bar<<<1, 128>>>();
    rec_kernel<<<128, 256, SMEM>>>(xg, W_hh0, h0);
    gemm_xg<256, false><<<gg, 256>>>(h0, W_ih1, b_ih1, b_hh1, xg);
    reset_bar<<<1, 128>>>();
    rec_kernel<<<128, 256, SMEM>>>(xg, W_hh1, h1);
    head_kernel<<<256, 256>>>(W_head, b_head, out);
}